// round 13
// baseline (speedup 1.0000x reference)
#include <cuda_runtime.h>

#define N_NODES 50000
#define HYPER_DIM 128
#define NNZ 800000
#define LEAKY 0.2f
#define LN_EPS 1e-5f
#define FULL 0xFFFFFFFFu

#define CAP 64                        // bucket capacity (max degree ~35, 12-sigma safe)
#define E4GRID ((NNZ / 4 + 255) / 256)
#define NGRID ((N_NODES * 32 + 255) / 256)   // 6250 blocks, warp per node

// ---------------------------------------------------------------------------
// Scratch (allocation-free __device__ globals).
// g_cntA/g_cntB are zero at module load; the LAST SpMM of every call
// re-zeroes them, so each kernel_launch invocation starts clean.
// ---------------------------------------------------------------------------
__device__ int g_cntA[N_NODES];
__device__ int g_cntB[N_NODES];
__device__ int2 g_edgeA[(size_t)N_NODES * CAP];  // bucketed by col: {row, val}
__device__ int2 g_edgeB[(size_t)N_NODES * CAP];  // bucketed by row: {col, val}
__device__ float g_ht[(size_t)N_NODES * HYPER_DIM];
__device__ float g_embs[(size_t)N_NODES * HYPER_DIM];

// ---------------------------------------------------------------------------
// 1. scatter into fixed-cap buckets, both orientations, 4 edges/thread.
// ---------------------------------------------------------------------------
__global__ void scatter_kernel(const int4* __restrict__ rows4,
                               const int4* __restrict__ cols4,
                               const float4* __restrict__ vals4) {
    int i = blockIdx.x * blockDim.x + threadIdx.x;
    if (i >= NNZ / 4) return;
    int4 r = rows4[i];
    int4 c = cols4[i];
    float4 v = vals4[i];

    int p0 = atomicAdd(&g_cntA[c.x], 1);
    int p1 = atomicAdd(&g_cntA[c.y], 1);
    int p2 = atomicAdd(&g_cntA[c.z], 1);
    int p3 = atomicAdd(&g_cntA[c.w], 1);
    g_edgeA[(size_t)c.x * CAP + p0] = make_int2(r.x, __float_as_int(v.x));
    g_edgeA[(size_t)c.y * CAP + p1] = make_int2(r.y, __float_as_int(v.y));
    g_edgeA[(size_t)c.z * CAP + p2] = make_int2(r.z, __float_as_int(v.z));
    g_edgeA[(size_t)c.w * CAP + p3] = make_int2(r.w, __float_as_int(v.w));

    int q0 = atomicAdd(&g_cntB[r.x], 1);
    int q1 = atomicAdd(&g_cntB[r.y], 1);
    int q2 = atomicAdd(&g_cntB[r.z], 1);
    int q3 = atomicAdd(&g_cntB[r.w], 1);
    g_edgeB[(size_t)r.x * CAP + q0] = make_int2(c.x, __float_as_int(v.x));
    g_edgeB[(size_t)r.y * CAP + q1] = make_int2(c.y, __float_as_int(v.y));
    g_edgeB[(size_t)r.z * CAP + q2] = make_int2(c.z, __float_as_int(v.z));
    g_edgeB[(size_t)r.w * CAP + q3] = make_int2(c.w, __float_as_int(v.w));
}

// ---------------------------------------------------------------------------
// 2. gather SpMM: warp per node. Edge metadata read via warp-UNIFORM loads
//    (all lanes same address -> 1 wavefront L1 broadcast, no shfl).
//    fp32 accumulate; optional fused leaky + LayerNorm + residual.
// ---------------------------------------------------------------------------
template <int FUSE_LN, int DO_LEAKY, int ZERO_CNT>
__global__ void gather_spmm_kernel(const int* __restrict__ cnt,
                                   const int2* __restrict__ edge,
                                   const float* __restrict__ x,
                                   const float* __restrict__ gamma,
                                   const float* __restrict__ beta,
                                   const float* __restrict__ res,
                                   float* __restrict__ out) {
    int n = (blockIdx.x * blockDim.x + threadIdx.x) >> 5;
    if (n >= N_NODES) return;
    int lane = threadIdx.x & 31;

    int deg = cnt[n];
    const int2* bucket = edge + (size_t)n * CAP;

    if (ZERO_CNT) {   // retire counters for next launch (this kernel is last)
        if (lane == 0) g_cntA[n] = 0;
        if (lane == 1) g_cntB[n] = 0;
    }

    const float4* xr = reinterpret_cast<const float4*>(x);
    float4 acc = make_float4(0.f, 0.f, 0.f, 0.f);

    #pragma unroll 4
    for (int k = 0; k < deg; k++) {
        int2 e = __ldg(&bucket[k]);                  // uniform: L1 broadcast
        float v = __int_as_float(e.y);
        float4 a = __ldg(&xr[(size_t)e.x * 32 + lane]);
        acc.x += v * a.x;
        acc.y += v * a.y;
        acc.z += v * a.z;
        acc.w += v * a.w;
    }

    if (FUSE_LN) {
        if (DO_LEAKY) {
            acc.x = acc.x >= 0.f ? acc.x : LEAKY * acc.x;
            acc.y = acc.y >= 0.f ? acc.y : LEAKY * acc.y;
            acc.z = acc.z >= 0.f ? acc.z : LEAKY * acc.z;
            acc.w = acc.w >= 0.f ? acc.w : LEAKY * acc.w;
        }
        float s = acc.x + acc.y + acc.z + acc.w;
        #pragma unroll
        for (int m = 16; m > 0; m >>= 1) s += __shfl_xor_sync(FULL, s, m);
        float mu = s * (1.f / HYPER_DIM);

        float dx = acc.x - mu, dy = acc.y - mu, dz = acc.z - mu, dw = acc.w - mu;
        float sq = dx * dx + dy * dy + dz * dz + dw * dw;
        #pragma unroll
        for (int m = 16; m > 0; m >>= 1) sq += __shfl_xor_sync(FULL, sq, m);
        float rstd = rsqrtf(sq * (1.f / HYPER_DIM) + LN_EPS);

        float4 g = reinterpret_cast<const float4*>(gamma)[lane];
        float4 b = reinterpret_cast<const float4*>(beta)[lane];
        float4 r = reinterpret_cast<const float4*>(res + (size_t)n * HYPER_DIM)[lane];

        acc.x = dx * rstd * g.x + b.x + r.x;
        acc.y = dy * rstd * g.y + b.y + r.y;
        acc.z = dz * rstd * g.z + b.z + r.z;
        acc.w = dw * rstd * g.w + b.w + r.w;
    }

    reinterpret_cast<float4*>(out + (size_t)n * HYPER_DIM)[lane] = acc;
}

// ---------------------------------------------------------------------------
// Launch: 5 kernels total.
// ---------------------------------------------------------------------------
extern "C" void kernel_launch(void* const* d_in, const int* in_sizes, int n_in,
                              void* d_out, int out_size) {
    const float* ego   = (const float*)d_in[0];
    const float* vals  = (const float*)d_in[1];
    const float* gamma = (const float*)d_in[2];   // [2, 128]
    const float* beta  = (const float*)d_in[3];   // [2, 128]
    const int*   rows  = (const int*)d_in[4];
    const int*   cols  = (const int*)d_in[5];
    float* out = (float*)d_out;

    float* ht; cudaGetSymbolAddress((void**)&ht, g_ht);
    float* em; cudaGetSymbolAddress((void**)&em, g_embs);
    int *cntA, *cntB; int2 *edgeA, *edgeB;
    cudaGetSymbolAddress((void**)&cntA, g_cntA);
    cudaGetSymbolAddress((void**)&cntB, g_cntB);
    cudaGetSymbolAddress((void**)&edgeA, g_edgeA);
    cudaGetSymbolAddress((void**)&edgeB, g_edgeB);

    // ---- bucket build (counters pre-zeroed by previous call / load) ----
    scatter_kernel<<<E4GRID, 256>>>((const int4*)rows, (const int4*)cols,
                                    (const float4*)vals);

    // ---- Layer 0 ----
    gather_spmm_kernel<0, 0, 0><<<NGRID, 256>>>(cntA, edgeA, ego,
                                                nullptr, nullptr, nullptr, ht);
    gather_spmm_kernel<1, 1, 0><<<NGRID, 256>>>(cntB, edgeB, ht,
                                                gamma, beta, ego, em);

    // ---- Layer 1 ----
    gather_spmm_kernel<0, 0, 0><<<NGRID, 256>>>(cntA, edgeA, em,
                                                nullptr, nullptr, nullptr, ht);
    gather_spmm_kernel<1, 0, 1><<<NGRID, 256>>>(cntB, edgeB, ht,
                                                gamma + HYPER_DIM, beta + HYPER_DIM,
                                                ego, out);
}

// round 14
// speedup vs baseline: 1.0968x; 1.0968x over previous
#include <cuda_runtime.h>

#define N_NODES 50000
#define HYPER_DIM 128
#define NNZ 800000
#define LEAKY 0.2f
#define LN_EPS 1e-5f
#define FULL 0xFFFFFFFFu

#define CAP 64                        // bucket capacity (max degree ~35, 12-sigma safe)
#define E4GRID ((NNZ / 4 + 255) / 256)
#define NGRID ((N_NODES * 32 + 255) / 256)   // 6250 blocks, warp per node

// ---------------------------------------------------------------------------
// Scratch (allocation-free __device__ globals).
// g_cntA/g_cntB are zero at module load; the LAST SpMM of every call
// re-zeroes them, so each kernel_launch invocation starts clean.
// ---------------------------------------------------------------------------
__device__ int g_cntA[N_NODES];
__device__ int g_cntB[N_NODES];
__device__ int2 g_edgeA[(size_t)N_NODES * CAP];  // bucketed by col: {row, val}
__device__ int2 g_edgeB[(size_t)N_NODES * CAP];  // bucketed by row: {col, val}
__device__ float g_ht[(size_t)N_NODES * HYPER_DIM];
__device__ float g_embs[(size_t)N_NODES * HYPER_DIM];

// ---------------------------------------------------------------------------
// 1. scatter into fixed-cap buckets, both orientations, 4 edges/thread.
// ---------------------------------------------------------------------------
__global__ void scatter_kernel(const int4* __restrict__ rows4,
                               const int4* __restrict__ cols4,
                               const float4* __restrict__ vals4) {
    int i = blockIdx.x * blockDim.x + threadIdx.x;
    if (i >= NNZ / 4) return;
    int4 r = rows4[i];
    int4 c = cols4[i];
    float4 v = vals4[i];

    int p0 = atomicAdd(&g_cntA[c.x], 1);
    int p1 = atomicAdd(&g_cntA[c.y], 1);
    int p2 = atomicAdd(&g_cntA[c.z], 1);
    int p3 = atomicAdd(&g_cntA[c.w], 1);
    g_edgeA[(size_t)c.x * CAP + p0] = make_int2(r.x, __float_as_int(v.x));
    g_edgeA[(size_t)c.y * CAP + p1] = make_int2(r.y, __float_as_int(v.y));
    g_edgeA[(size_t)c.z * CAP + p2] = make_int2(r.z, __float_as_int(v.z));
    g_edgeA[(size_t)c.w * CAP + p3] = make_int2(r.w, __float_as_int(v.w));

    int q0 = atomicAdd(&g_cntB[r.x], 1);
    int q1 = atomicAdd(&g_cntB[r.y], 1);
    int q2 = atomicAdd(&g_cntB[r.z], 1);
    int q3 = atomicAdd(&g_cntB[r.w], 1);
    g_edgeB[(size_t)r.x * CAP + q0] = make_int2(c.x, __float_as_int(v.x));
    g_edgeB[(size_t)r.y * CAP + q1] = make_int2(c.y, __float_as_int(v.y));
    g_edgeB[(size_t)r.z * CAP + q2] = make_int2(c.z, __float_as_int(v.z));
    g_edgeB[(size_t)r.w * CAP + q3] = make_int2(c.w, __float_as_int(v.w));
}

// ---------------------------------------------------------------------------
// 2a. plain gather SpMM: warp per node, shfl-broadcast edges, reg accumulator.
//     __launch_bounds__(256, 8) -> regs<=32 -> up to 64 warps/SM for MLP.
// ---------------------------------------------------------------------------
__global__ void __launch_bounds__(256, 8)
gather_spmm_plain_kernel(const int* __restrict__ cnt,
                         const int2* __restrict__ edge,
                         const float* __restrict__ x,
                         float* __restrict__ out) {
    int n = (blockIdx.x * blockDim.x + threadIdx.x) >> 5;
    if (n >= N_NODES) return;
    int lane = threadIdx.x & 31;

    int deg = cnt[n];
    const int2* bucket = edge + (size_t)n * CAP;

    const float4* xr = reinterpret_cast<const float4*>(x);
    float4 acc = make_float4(0.f, 0.f, 0.f, 0.f);

    for (int base = 0; base < deg; base += 32) {
        int k = base + lane;
        int2 ev = (k < deg) ? bucket[k] : make_int2(0, 0);
        int m = min(32, deg - base);
        #pragma unroll 8
        for (int t = 0; t < m; t++) {
            int jj   = __shfl_sync(FULL, ev.x, t);
            float vv = __int_as_float(__shfl_sync(FULL, ev.y, t));
            float4 a = xr[(size_t)jj * 32 + lane];
            acc.x += vv * a.x;
            acc.y += vv * a.y;
            acc.z += vv * a.z;
            acc.w += vv * a.w;
        }
    }

    reinterpret_cast<float4*>(out + (size_t)n * HYPER_DIM)[lane] = acc;
}

// ---------------------------------------------------------------------------
// 2b. gather SpMM + fused leaky/LayerNorm/residual epilogue.
// ---------------------------------------------------------------------------
template <int DO_LEAKY, int ZERO_CNT>
__global__ void __launch_bounds__(256, 6)
gather_spmm_ln_kernel(const int* __restrict__ cnt,
                      const int2* __restrict__ edge,
                      const float* __restrict__ x,
                      const float* __restrict__ gamma,
                      const float* __restrict__ beta,
                      const float* __restrict__ res,
                      float* __restrict__ out) {
    int n = (blockIdx.x * blockDim.x + threadIdx.x) >> 5;
    if (n >= N_NODES) return;
    int lane = threadIdx.x & 31;

    int deg = cnt[n];
    const int2* bucket = edge + (size_t)n * CAP;

    if (ZERO_CNT) {   // retire counters for next launch (this kernel is last)
        if (lane == 0) g_cntA[n] = 0;
        if (lane == 1) g_cntB[n] = 0;
    }

    const float4* xr = reinterpret_cast<const float4*>(x);
    float4 acc = make_float4(0.f, 0.f, 0.f, 0.f);

    for (int base = 0; base < deg; base += 32) {
        int k = base + lane;
        int2 ev = (k < deg) ? bucket[k] : make_int2(0, 0);
        int m = min(32, deg - base);
        #pragma unroll 8
        for (int t = 0; t < m; t++) {
            int jj   = __shfl_sync(FULL, ev.x, t);
            float vv = __int_as_float(__shfl_sync(FULL, ev.y, t));
            float4 a = xr[(size_t)jj * 32 + lane];
            acc.x += vv * a.x;
            acc.y += vv * a.y;
            acc.z += vv * a.z;
            acc.w += vv * a.w;
        }
    }

    if (DO_LEAKY) {
        acc.x = acc.x >= 0.f ? acc.x : LEAKY * acc.x;
        acc.y = acc.y >= 0.f ? acc.y : LEAKY * acc.y;
        acc.z = acc.z >= 0.f ? acc.z : LEAKY * acc.z;
        acc.w = acc.w >= 0.f ? acc.w : LEAKY * acc.w;
    }
    float s = acc.x + acc.y + acc.z + acc.w;
    #pragma unroll
    for (int m = 16; m > 0; m >>= 1) s += __shfl_xor_sync(FULL, s, m);
    float mu = s * (1.f / HYPER_DIM);

    float dx = acc.x - mu, dy = acc.y - mu, dz = acc.z - mu, dw = acc.w - mu;
    float sq = dx * dx + dy * dy + dz * dz + dw * dw;
    #pragma unroll
    for (int m = 16; m > 0; m >>= 1) sq += __shfl_xor_sync(FULL, sq, m);
    float rstd = rsqrtf(sq * (1.f / HYPER_DIM) + LN_EPS);

    float4 g = reinterpret_cast<const float4*>(gamma)[lane];
    float4 b = reinterpret_cast<const float4*>(beta)[lane];
    float4 r = reinterpret_cast<const float4*>(res + (size_t)n * HYPER_DIM)[lane];

    acc.x = dx * rstd * g.x + b.x + r.x;
    acc.y = dy * rstd * g.y + b.y + r.y;
    acc.z = dz * rstd * g.z + b.z + r.z;
    acc.w = dw * rstd * g.w + b.w + r.w;

    reinterpret_cast<float4*>(out + (size_t)n * HYPER_DIM)[lane] = acc;
}

// ---------------------------------------------------------------------------
// Launch: 5 kernels total.
// ---------------------------------------------------------------------------
extern "C" void kernel_launch(void* const* d_in, const int* in_sizes, int n_in,
                              void* d_out, int out_size) {
    const float* ego   = (const float*)d_in[0];
    const float* vals  = (const float*)d_in[1];
    const float* gamma = (const float*)d_in[2];   // [2, 128]
    const float* beta  = (const float*)d_in[3];   // [2, 128]
    const int*   rows  = (const int*)d_in[4];
    const int*   cols  = (const int*)d_in[5];
    float* out = (float*)d_out;

    float* ht; cudaGetSymbolAddress((void**)&ht, g_ht);
    float* em; cudaGetSymbolAddress((void**)&em, g_embs);
    int *cntA, *cntB; int2 *edgeA, *edgeB;
    cudaGetSymbolAddress((void**)&cntA, g_cntA);
    cudaGetSymbolAddress((void**)&cntB, g_cntB);
    cudaGetSymbolAddress((void**)&edgeA, g_edgeA);
    cudaGetSymbolAddress((void**)&edgeB, g_edgeB);

    // ---- bucket build (counters pre-zeroed by previous call / load) ----
    scatter_kernel<<<E4GRID, 256>>>((const int4*)rows, (const int4*)cols,
                                    (const float4*)vals);

    // ---- Layer 0 ----
    gather_spmm_plain_kernel<<<NGRID, 256>>>(cntA, edgeA, ego, ht);
    gather_spmm_ln_kernel<1, 0><<<NGRID, 256>>>(cntB, edgeB, ht,
                                                gamma, beta, ego, em);

    // ---- Layer 1 ----
    gather_spmm_plain_kernel<<<NGRID, 256>>>(cntA, edgeA, em, ht);
    gather_spmm_ln_kernel<0, 1><<<NGRID, 256>>>(cntB, edgeB, ht,
                                                gamma + HYPER_DIM, beta + HYPER_DIM,
                                                ego, out);
}

// round 16
// speedup vs baseline: 1.3320x; 1.2145x over previous
#include <cuda_runtime.h>
#include <cuda_fp16.h>

#define N_NODES 50000
#define HYPER_DIM 128
#define NNZ 800000
#define LEAKY 0.2f
#define LN_EPS 1e-5f
#define FULL 0xFFFFFFFFu

#define CAP 64                        // bucket capacity (max degree ~35, 12-sigma safe)
#define E4GRID ((NNZ / 4 + 255) / 256)
#define NGRID ((N_NODES * 32 + 255) / 256)   // 6250 blocks, warp per node
#define N4 (N_NODES * HYPER_DIM / 4)

// ---------------------------------------------------------------------------
// Bit-cast helpers (portable across toolkit versions)
// ---------------------------------------------------------------------------
__device__ __forceinline__ unsigned h2_to_u32(__half2 h) {
    return *reinterpret_cast<unsigned*>(&h);
}
__device__ __forceinline__ __half2 u32_to_h2(unsigned u) {
    return *reinterpret_cast<__half2*>(&u);
}

// ---------------------------------------------------------------------------
// Scratch (allocation-free __device__ globals).
// g_cntA/g_cntB zero at load; last SpMM of each call re-zeroes them.
// Edge packed as uint32: low 16 bits = neighbor idx (50000 < 65536),
// high 16 bits = fp16 edge value.
// ---------------------------------------------------------------------------
__device__ int g_cntA[N_NODES];
__device__ int g_cntB[N_NODES];
__device__ unsigned g_edgeA[(size_t)N_NODES * CAP];  // bucketed by col: {row|val}
__device__ unsigned g_edgeB[(size_t)N_NODES * CAP];  // bucketed by row: {col|val}
__device__ __half g_x16[(size_t)N_NODES * HYPER_DIM];   // fp16 feature stage
__device__ __half g_ht16[(size_t)N_NODES * HYPER_DIM];  // fp16 intermediate

__device__ __forceinline__ unsigned pack_edge(int idx, float v) {
    __half h = __float2half_rn(v);
    unsigned hv = (unsigned)__half_as_ushort(h);
    return (unsigned)idx | (hv << 16);
}

// ---------------------------------------------------------------------------
// 1. fp32 -> fp16 conversion of ego (thread = 4 features)
// ---------------------------------------------------------------------------
__global__ void conv16_kernel(const float4* __restrict__ src,
                              uint2* __restrict__ dst) {
    int i = blockIdx.x * blockDim.x + threadIdx.x;
    if (i >= N4) return;
    float4 a = src[i];
    uint2 o;
    o.x = h2_to_u32(__floats2half2_rn(a.x, a.y));
    o.y = h2_to_u32(__floats2half2_rn(a.z, a.w));
    dst[i] = o;
}

// ---------------------------------------------------------------------------
// 2. scatter packed edges into fixed-cap buckets, both orientations.
// ---------------------------------------------------------------------------
__global__ void scatter_kernel(const int4* __restrict__ rows4,
                               const int4* __restrict__ cols4,
                               const float4* __restrict__ vals4) {
    int i = blockIdx.x * blockDim.x + threadIdx.x;
    if (i >= NNZ / 4) return;
    int4 r = rows4[i];
    int4 c = cols4[i];
    float4 v = vals4[i];

    int p0 = atomicAdd(&g_cntA[c.x], 1);
    int p1 = atomicAdd(&g_cntA[c.y], 1);
    int p2 = atomicAdd(&g_cntA[c.z], 1);
    int p3 = atomicAdd(&g_cntA[c.w], 1);
    g_edgeA[(size_t)c.x * CAP + p0] = pack_edge(r.x, v.x);
    g_edgeA[(size_t)c.y * CAP + p1] = pack_edge(r.y, v.y);
    g_edgeA[(size_t)c.z * CAP + p2] = pack_edge(r.z, v.z);
    g_edgeA[(size_t)c.w * CAP + p3] = pack_edge(r.w, v.w);

    int q0 = atomicAdd(&g_cntB[r.x], 1);
    int q1 = atomicAdd(&g_cntB[r.y], 1);
    int q2 = atomicAdd(&g_cntB[r.z], 1);
    int q3 = atomicAdd(&g_cntB[r.w], 1);
    g_edgeB[(size_t)r.x * CAP + q0] = pack_edge(c.x, v.x);
    g_edgeB[(size_t)r.y * CAP + q1] = pack_edge(c.y, v.y);
    g_edgeB[(size_t)r.z * CAP + q2] = pack_edge(c.z, v.z);
    g_edgeB[(size_t)r.w * CAP + q3] = pack_edge(c.w, v.w);
}

// ---------------------------------------------------------------------------
// Shared SpMM inner loop: fp16 gathers (8B/lane), fp32 accumulation.
// ---------------------------------------------------------------------------
__device__ __forceinline__ float4 spmm_accum(int deg, const unsigned* bucket,
                                             const uint2* __restrict__ xr,
                                             int lane) {
    float4 acc = make_float4(0.f, 0.f, 0.f, 0.f);
    for (int base = 0; base < deg; base += 32) {
        int k = base + lane;
        unsigned ev = (k < deg) ? bucket[k] : 0u;
        int m = min(32, deg - base);
        #pragma unroll 8
        for (int t = 0; t < m; t++) {
            unsigned e = __shfl_sync(FULL, ev, t);
            int jj = (int)(e & 0xFFFFu);
            float vv = __half2float(__ushort_as_half((unsigned short)(e >> 16)));
            uint2 raw = xr[(size_t)jj * 32 + lane];
            float2 f01 = __half22float2(u32_to_h2(raw.x));
            float2 f23 = __half22float2(u32_to_h2(raw.y));
            acc.x += vv * f01.x;
            acc.y += vv * f01.y;
            acc.z += vv * f23.x;
            acc.w += vv * f23.y;
        }
    }
    return acc;
}

__device__ __forceinline__ uint2 pack4(float4 a) {
    uint2 o;
    o.x = h2_to_u32(__floats2half2_rn(a.x, a.y));
    o.y = h2_to_u32(__floats2half2_rn(a.z, a.w));
    return o;
}

// ---------------------------------------------------------------------------
// 3a. plain gather SpMM: fp16 in, fp16 out.
// ---------------------------------------------------------------------------
__global__ void __launch_bounds__(256, 8)
gather_spmm_plain_kernel(const int* __restrict__ cnt,
                         const unsigned* __restrict__ edge,
                         const __half* __restrict__ x,
                         __half* __restrict__ out) {
    int n = (blockIdx.x * blockDim.x + threadIdx.x) >> 5;
    if (n >= N_NODES) return;
    int lane = threadIdx.x & 31;

    int deg = cnt[n];
    const unsigned* bucket = edge + (size_t)n * CAP;
    float4 acc = spmm_accum(deg, bucket, reinterpret_cast<const uint2*>(x), lane);
    reinterpret_cast<uint2*>(out)[(size_t)n * 32 + lane] = pack4(acc);
}

// ---------------------------------------------------------------------------
// 3b. gather SpMM + fused leaky/LayerNorm/residual.
//     OUT_HALF: fp16 (feeds next layer) or fp32 (final output).
// ---------------------------------------------------------------------------
template <int DO_LEAKY, int ZERO_CNT, int OUT_HALF>
__global__ void __launch_bounds__(256, 8)
gather_spmm_ln_kernel(const int* __restrict__ cnt,
                      const unsigned* __restrict__ edge,
                      const __half* __restrict__ x,
                      const float* __restrict__ gamma,
                      const float* __restrict__ beta,
                      const float* __restrict__ res,
                      float* __restrict__ out_f,
                      __half* __restrict__ out_h) {
    int n = (blockIdx.x * blockDim.x + threadIdx.x) >> 5;
    if (n >= N_NODES) return;
    int lane = threadIdx.x & 31;

    int deg = cnt[n];
    const unsigned* bucket = edge + (size_t)n * CAP;

    if (ZERO_CNT) {   // retire counters for next launch (this kernel is last)
        if (lane == 0) g_cntA[n] = 0;
        if (lane == 1) g_cntB[n] = 0;
    }

    float4 acc = spmm_accum(deg, bucket, reinterpret_cast<const uint2*>(x), lane);

    if (DO_LEAKY) {
        acc.x = acc.x >= 0.f ? acc.x : LEAKY * acc.x;
        acc.y = acc.y >= 0.f ? acc.y : LEAKY * acc.y;
        acc.z = acc.z >= 0.f ? acc.z : LEAKY * acc.z;
        acc.w = acc.w >= 0.f ? acc.w : LEAKY * acc.w;
    }
    float s = acc.x + acc.y + acc.z + acc.w;
    #pragma unroll
    for (int m = 16; m > 0; m >>= 1) s += __shfl_xor_sync(FULL, s, m);
    float mu = s * (1.f / HYPER_DIM);

    float dx = acc.x - mu, dy = acc.y - mu, dz = acc.z - mu, dw = acc.w - mu;
    float sq = dx * dx + dy * dy + dz * dz + dw * dw;
    #pragma unroll
    for (int m = 16; m > 0; m >>= 1) sq += __shfl_xor_sync(FULL, sq, m);
    float rstd = rsqrtf(sq * (1.f / HYPER_DIM) + LN_EPS);

    float4 g = reinterpret_cast<const float4*>(gamma)[lane];
    float4 b = reinterpret_cast<const float4*>(beta)[lane];
    float4 r = reinterpret_cast<const float4*>(res + (size_t)n * HYPER_DIM)[lane];

    acc.x = dx * rstd * g.x + b.x + r.x;
    acc.y = dy * rstd * g.y + b.y + r.y;
    acc.z = dz * rstd * g.z + b.z + r.z;
    acc.w = dw * rstd * g.w + b.w + r.w;

    if (OUT_HALF) {
        reinterpret_cast<uint2*>(out_h)[(size_t)n * 32 + lane] = pack4(acc);
    } else {
        reinterpret_cast<float4*>(out_f + (size_t)n * HYPER_DIM)[lane] = acc;
    }
}

// ---------------------------------------------------------------------------
// Launch: 6 kernels total.
// ---------------------------------------------------------------------------
extern "C" void kernel_launch(void* const* d_in, const int* in_sizes, int n_in,
                              void* d_out, int out_size) {
    const float* ego   = (const float*)d_in[0];
    const float* vals  = (const float*)d_in[1];
    const float* gamma = (const float*)d_in[2];   // [2, 128]
    const float* beta  = (const float*)d_in[3];   // [2, 128]
    const int*   rows  = (const int*)d_in[4];
    const int*   cols  = (const int*)d_in[5];
    float* out = (float*)d_out;

    __half *x16, *ht16;
    cudaGetSymbolAddress((void**)&x16,  g_x16);
    cudaGetSymbolAddress((void**)&ht16, g_ht16);
    int *cntA, *cntB; unsigned *edgeA, *edgeB;
    cudaGetSymbolAddress((void**)&cntA, g_cntA);
    cudaGetSymbolAddress((void**)&cntB, g_cntB);
    cudaGetSymbolAddress((void**)&edgeA, g_edgeA);
    cudaGetSymbolAddress((void**)&edgeB, g_edgeB);

    // ---- staging + bucket build (counters pre-zeroed by previous call) ----
    conv16_kernel<<<(N4 + 255) / 256, 256>>>((const float4*)ego, (uint2*)x16);
    scatter_kernel<<<E4GRID, 256>>>((const int4*)rows, (const int4*)cols,
                                    (const float4*)vals);

    // ---- Layer 0 ----
    //  ht16 = A @ x16
    gather_spmm_plain_kernel<<<NGRID, 256>>>(cntA, edgeA, x16, ht16);
    //  x16 = half( LN(leaky(B @ ht16)) * g0 + b0 + ego )
    gather_spmm_ln_kernel<1, 0, 1><<<NGRID, 256>>>(cntB, edgeB, ht16,
                                                   gamma, beta, ego,
                                                   nullptr, x16);

    // ---- Layer 1 ----
    gather_spmm_plain_kernel<<<NGRID, 256>>>(cntA, edgeA, x16, ht16);
    //  out = LN(B @ ht16) * g1 + b1 + ego   (fp32 final; re-zero counters)
    gather_spmm_ln_kernel<0, 1, 0><<<NGRID, 256>>>(cntB, edgeB, ht16,
                                                   gamma + HYPER_DIM, beta + HYPER_DIM,
                                                   ego, out, nullptr);
}

// round 17
// speedup vs baseline: 1.3709x; 1.0291x over previous
#include <cuda_runtime.h>
#include <cuda_fp16.h>

#define N_NODES 50000
#define HYPER_DIM 128
#define NNZ 800000
#define LEAKY 0.2f
#define LN_EPS 1e-5f
#define FULL 0xFFFFFFFFu

#define CAP 64                        // bucket capacity (max degree ~35, 12-sigma safe)
#define E4GRID ((NNZ / 4 + 255) / 256)            // 782
#define N4 (N_NODES * HYPER_DIM / 4)              // 1.6M float4s
#define CONVGRID ((N4 + 255) / 256)               // 6250
#define NGRID ((N_NODES * 32 + 255) / 256)        // 6250, warp per node

// ---------------------------------------------------------------------------
// Bit-cast helpers
// ---------------------------------------------------------------------------
__device__ __forceinline__ unsigned h2_to_u32(__half2 h) {
    return *reinterpret_cast<unsigned*>(&h);
}
__device__ __forceinline__ __half2 u32_to_h2(unsigned u) {
    return *reinterpret_cast<__half2*>(&u);
}

// ---------------------------------------------------------------------------
// Scratch (allocation-free __device__ globals).
// g_cntA/g_cntB zero at load; last SpMM of each call re-zeroes them.
// Edge packed as uint32: low 16 = neighbor idx (<65536), high 16 = fp16 val.
// Bucket slots in [deg, CAP) are NEVER written -> stay zero (static init),
// so padded reads contribute exactly 0 to the accumulation.
// ---------------------------------------------------------------------------
__device__ int g_cntA[N_NODES];
__device__ int g_cntB[N_NODES];
__device__ unsigned g_edgeA[(size_t)N_NODES * CAP];   // bucketed by col: {row|val}
__device__ unsigned g_edgeB[(size_t)N_NODES * CAP];   // bucketed by row: {col|val}
__device__ __half g_ego16[(size_t)N_NODES * HYPER_DIM];  // fp16 ego (residual + L0 input)
__device__ __half g_ht16[(size_t)N_NODES * HYPER_DIM];   // fp16 intermediate
__device__ __half g_em16[(size_t)N_NODES * HYPER_DIM];   // fp16 embs after layer 0

__device__ __forceinline__ unsigned pack_edge(int idx, float v) {
    __half h = __float2half_rn(v);
    unsigned hv = (unsigned)__half_as_ushort(h);
    return (unsigned)idx | (hv << 16);
}

// ---------------------------------------------------------------------------
// 1. fused front kernel: blocks [0, E4GRID) scatter packed edges into both
//    bucket orientations; blocks [E4GRID, ..) convert ego fp32 -> fp16.
//    The two roles touch disjoint data.
// ---------------------------------------------------------------------------
__global__ void front_kernel(const int4* __restrict__ rows4,
                             const int4* __restrict__ cols4,
                             const float4* __restrict__ vals4,
                             const float4* __restrict__ ego) {
    if (blockIdx.x < E4GRID) {
        int i = blockIdx.x * blockDim.x + threadIdx.x;
        if (i >= NNZ / 4) return;
        int4 r = rows4[i];
        int4 c = cols4[i];
        float4 v = vals4[i];

        int p0 = atomicAdd(&g_cntA[c.x], 1);
        int p1 = atomicAdd(&g_cntA[c.y], 1);
        int p2 = atomicAdd(&g_cntA[c.z], 1);
        int p3 = atomicAdd(&g_cntA[c.w], 1);
        g_edgeA[(size_t)c.x * CAP + p0] = pack_edge(r.x, v.x);
        g_edgeA[(size_t)c.y * CAP + p1] = pack_edge(r.y, v.y);
        g_edgeA[(size_t)c.z * CAP + p2] = pack_edge(r.z, v.z);
        g_edgeA[(size_t)c.w * CAP + p3] = pack_edge(r.w, v.w);

        int q0 = atomicAdd(&g_cntB[r.x], 1);
        int q1 = atomicAdd(&g_cntB[r.y], 1);
        int q2 = atomicAdd(&g_cntB[r.z], 1);
        int q3 = atomicAdd(&g_cntB[r.w], 1);
        g_edgeB[(size_t)r.x * CAP + q0] = pack_edge(c.x, v.x);
        g_edgeB[(size_t)r.y * CAP + q1] = pack_edge(c.y, v.y);
        g_edgeB[(size_t)r.z * CAP + q2] = pack_edge(c.z, v.z);
        g_edgeB[(size_t)r.w * CAP + q3] = pack_edge(c.w, v.w);
    } else {
        int i = (blockIdx.x - E4GRID) * blockDim.x + threadIdx.x;
        if (i >= N4) return;
        float4 a = ego[i];
        uint2 o;
        o.x = h2_to_u32(__floats2half2_rn(a.x, a.y));
        o.y = h2_to_u32(__floats2half2_rn(a.z, a.w));
        reinterpret_cast<uint2*>(g_ego16)[i] = o;
    }
}

// ---------------------------------------------------------------------------
// Core accumulation: half-warp-per-edge. Half-warp h (lane>>4) processes
// edge t+h; lane covers 8 features (one uint4 = 8 fp16). fp32 accumulation.
// After the loop, halves are combined -> every lane holds the full sums for
// features [8*(lane&15), 8*(lane&15)+8).
// ---------------------------------------------------------------------------
__device__ __forceinline__ void spmm_accum16(int deg,
                                             const unsigned* __restrict__ bucket,
                                             const uint4* __restrict__ xr,
                                             int lane, int sub, int half,
                                             float acc[8]) {
    #pragma unroll
    for (int i = 0; i < 8; i++) acc[i] = 0.f;

    for (int base = 0; base < deg; base += 32) {
        unsigned ev = bucket[base + lane];   // zero-padded to CAP: always safe
        int m = deg - base; if (m > 32) m = 32;
        #pragma unroll 4
        for (int t = 0; t < m; t += 2) {
            // per-lane src: half 0 -> edge t, half 1 -> edge t+1
            unsigned e = __shfl_sync(FULL, ev, t + half);
            float vv = __half2float(__ushort_as_half((unsigned short)(e >> 16)));
            int jj = (int)(e & 0xFFFFu);
            uint4 raw = xr[(size_t)jj * 16 + sub];
            float2 f0 = __half22float2(u32_to_h2(raw.x));
            float2 f1 = __half22float2(u32_to_h2(raw.y));
            float2 f2 = __half22float2(u32_to_h2(raw.z));
            float2 f3 = __half22float2(u32_to_h2(raw.w));
            acc[0] += vv * f0.x;  acc[1] += vv * f0.y;
            acc[2] += vv * f1.x;  acc[3] += vv * f1.y;
            acc[4] += vv * f2.x;  acc[5] += vv * f2.y;
            acc[6] += vv * f3.x;  acc[7] += vv * f3.y;
        }
    }
    // combine the two half-warps (after this, halves hold identical sums)
    #pragma unroll
    for (int i = 0; i < 8; i++)
        acc[i] += __shfl_xor_sync(FULL, acc[i], 16);
}

__device__ __forceinline__ uint4 pack8(const float acc[8]) {
    uint4 o;
    o.x = h2_to_u32(__floats2half2_rn(acc[0], acc[1]));
    o.y = h2_to_u32(__floats2half2_rn(acc[2], acc[3]));
    o.z = h2_to_u32(__floats2half2_rn(acc[4], acc[5]));
    o.w = h2_to_u32(__floats2half2_rn(acc[6], acc[7]));
    return o;
}

// ---------------------------------------------------------------------------
// 2a. plain gather SpMM: fp16 in, fp16 out.
// ---------------------------------------------------------------------------
__global__ void __launch_bounds__(256, 6)
gather_spmm_plain_kernel(const int* __restrict__ cnt,
                         const unsigned* __restrict__ edge,
                         const __half* __restrict__ x,
                         __half* __restrict__ out) {
    int n = (blockIdx.x * blockDim.x + threadIdx.x) >> 5;
    if (n >= N_NODES) return;
    int lane = threadIdx.x & 31;
    int half = lane >> 4;
    int sub  = lane & 15;

    float acc[8];
    spmm_accum16(cnt[n], edge + (size_t)n * CAP,
                 reinterpret_cast<const uint4*>(x), lane, sub, half, acc);

    if (half == 0)
        reinterpret_cast<uint4*>(out)[(size_t)n * 16 + sub] = pack8(acc);
}

// ---------------------------------------------------------------------------
// 2b. gather SpMM + fused leaky/LayerNorm/residual (residual read as fp16).
// ---------------------------------------------------------------------------
template <int DO_LEAKY, int ZERO_CNT, int OUT_HALF>
__global__ void __launch_bounds__(256, 6)
gather_spmm_ln_kernel(const int* __restrict__ cnt,
                      const unsigned* __restrict__ edge,
                      const __half* __restrict__ x,
                      const float* __restrict__ gamma,
                      const float* __restrict__ beta,
                      const __half* __restrict__ res16,
                      float* __restrict__ out_f,
                      __half* __restrict__ out_h) {
    int n = (blockIdx.x * blockDim.x + threadIdx.x) >> 5;
    if (n >= N_NODES) return;
    int lane = threadIdx.x & 31;
    int half = lane >> 4;
    int sub  = lane & 15;

    int deg = cnt[n];
    if (ZERO_CNT) {   // retire counters for next launch (this kernel is last)
        if (lane == 0) g_cntA[n] = 0;
        if (lane == 1) g_cntB[n] = 0;
    }

    float acc[8];
    spmm_accum16(deg, edge + (size_t)n * CAP,
                 reinterpret_cast<const uint4*>(x), lane, sub, half, acc);

    if (DO_LEAKY) {
        #pragma unroll
        for (int i = 0; i < 8; i++)
            acc[i] = acc[i] >= 0.f ? acc[i] : LEAKY * acc[i];
    }

    // mean: features are duplicated across the two halves -> divide by 256
    float s = 0.f;
    #pragma unroll
    for (int i = 0; i < 8; i++) s += acc[i];
    #pragma unroll
    for (int m = 16; m > 0; m >>= 1) s += __shfl_xor_sync(FULL, s, m);
    float mu = s * (1.f / 256.f);

    float sq = 0.f;
    #pragma unroll
    for (int i = 0; i < 8; i++) {
        acc[i] -= mu;
        sq += acc[i] * acc[i];
    }
    #pragma unroll
    for (int m = 16; m > 0; m >>= 1) sq += __shfl_xor_sync(FULL, sq, m);
    float rstd = rsqrtf(sq * (1.f / 256.f) + LN_EPS);

    const float4* g4 = reinterpret_cast<const float4*>(gamma);
    const float4* b4 = reinterpret_cast<const float4*>(beta);
    float4 g0 = g4[2 * sub], g1 = g4[2 * sub + 1];
    float4 b0 = b4[2 * sub], b1 = b4[2 * sub + 1];

    uint4 rr = reinterpret_cast<const uint4*>(res16)[(size_t)n * 16 + sub];
    float2 r0 = __half22float2(u32_to_h2(rr.x));
    float2 r1 = __half22float2(u32_to_h2(rr.y));
    float2 r2 = __half22float2(u32_to_h2(rr.z));
    float2 r3 = __half22float2(u32_to_h2(rr.w));

    float o[8];
    o[0] = acc[0] * rstd * g0.x + b0.x + r0.x;
    o[1] = acc[1] * rstd * g0.y + b0.y + r0.y;
    o[2] = acc[2] * rstd * g0.z + b0.z + r1.x;
    o[3] = acc[3] * rstd * g0.w + b0.w + r1.y;
    o[4] = acc[4] * rstd * g1.x + b1.x + r2.x;
    o[5] = acc[5] * rstd * g1.y + b1.y + r2.y;
    o[6] = acc[6] * rstd * g1.z + b1.z + r3.x;
    o[7] = acc[7] * rstd * g1.w + b1.w + r3.y;

    if (OUT_HALF) {
        if (half == 0)
            reinterpret_cast<uint4*>(out_h)[(size_t)n * 16 + sub] = pack8(o);
    } else {
        if (half == 0) {
            float4* of = reinterpret_cast<float4*>(out_f) + (size_t)n * 32 + 2 * sub;
            of[0] = make_float4(o[0], o[1], o[2], o[3]);
            of[1] = make_float4(o[4], o[5], o[6], o[7]);
        }
    }
}

// ---------------------------------------------------------------------------
// Launch: 5 kernels total.
// ---------------------------------------------------------------------------
extern "C" void kernel_launch(void* const* d_in, const int* in_sizes, int n_in,
                              void* d_out, int out_size) {
    const float* ego   = (const float*)d_in[0];
    const float* vals  = (const float*)d_in[1];
    const float* gamma = (const float*)d_in[2];   // [2, 128]
    const float* beta  = (const float*)d_in[3];   // [2, 128]
    const int*   rows  = (const int*)d_in[4];
    const int*   cols  = (const int*)d_in[5];
    float* out = (float*)d_out;

    __half *ego16, *ht16, *em16;
    cudaGetSymbolAddress((void**)&ego16, g_ego16);
    cudaGetSymbolAddress((void**)&ht16,  g_ht16);
    cudaGetSymbolAddress((void**)&em16,  g_em16);
    int *cntA, *cntB; unsigned *edgeA, *edgeB;
    cudaGetSymbolAddress((void**)&cntA, g_cntA);
    cudaGetSymbolAddress((void**)&cntB, g_cntB);
    cudaGetSymbolAddress((void**)&edgeA, g_edgeA);
    cudaGetSymbolAddress((void**)&edgeB, g_edgeB);

    // ---- scatter + fp16 staging, fused (counters pre-zeroed by prior call) --
    front_kernel<<<E4GRID + CONVGRID, 256>>>((const int4*)rows, (const int4*)cols,
                                             (const float4*)vals,
                                             (const float4*)ego);

    // ---- Layer 0 ----
    //  ht16 = A @ ego16
    gather_spmm_plain_kernel<<<NGRID, 256>>>(cntA, edgeA, ego16, ht16);
    //  em16 = half( LN(leaky(B @ ht16)) * g0 + b0 + ego16 )
    gather_spmm_ln_kernel<1, 0, 1><<<NGRID, 256>>>(cntB, edgeB, ht16,
                                                   gamma, beta, ego16,
                                                   nullptr, em16);

    // ---- Layer 1 ----
    gather_spmm_plain_kernel<<<NGRID, 256>>>(cntA, edgeA, em16, ht16);
    //  out = LN(B @ ht16) * g1 + b1 + ego16   (fp32 final; re-zero counters)
    gather_spmm_ln_kernel<0, 1, 0><<<NGRID, 256>>>(cntB, edgeB, ht16,
                                                   gamma + HYPER_DIM, beta + HYPER_DIM,
                                                   ego16, out, nullptr);
}